// round 16
// baseline (speedup 1.0000x reference)
#include <cuda_runtime.h>
#include <cuda_fp16.h>
#include <cstdint>

// Problem constants (fixed shapes)
constexpr int T_ = 2048;
constexpr int S_ = 2048;
constexpr int B_ = 2;
constexpr int E_ = 1024;
constexpr int H_ = 16;
constexpr int D_ = 64;
constexpr int M_ = T_ * B_;   // 4096

constexpr float LOG2E = 1.44269504088896f;

// ---------------------------------------------------------------------------
// Scratch (__device__ globals; allocations forbidden)
// ---------------------------------------------------------------------------
__device__ __half g_iq[M_ * E_];
__device__ __half g_ik[M_ * E_];
__device__ __half g_iv[M_ * E_];
__device__ __half g_w[4][E_ * E_];
__device__ __half g_pq[B_ * H_ * T_ * D_];   // Q single (pre-scaled by 0.125*log2e)
__device__ __half g_pk[B_ * H_ * S_ * D_];
__device__ __half g_pv[B_ * H_ * S_ * D_];
__device__ __half g_ch[M_ * E_];
__device__ __half g_mh[B_ * T_ * S_];        // merged mask, log2e-scaled

// ---------------------------------------------------------------------------
// PTX helpers (generic PTX only)
// ---------------------------------------------------------------------------
__device__ __forceinline__ uint32_t smem_u32(const void* p) {
    uint32_t a;
    asm("{ .reg .u64 t; cvta.to.shared.u64 t, %1; cvt.u32.u64 %0, t; }"
        : "=r"(a) : "l"(p));
    return a;
}
__device__ __forceinline__ void cp16(uint32_t dst, const void* src) {
    asm volatile("cp.async.cg.shared.global [%0], [%1], 16;" :: "r"(dst), "l"(src));
}
__device__ __forceinline__ void cp_commit() {
    asm volatile("cp.async.commit_group;" ::: "memory");
}
template <int N>
__device__ __forceinline__ void cp_wait() {
    asm volatile("cp.async.wait_group %0;" :: "n"(N) : "memory");
}
__device__ __forceinline__ void ldsm4(uint32_t& r0, uint32_t& r1, uint32_t& r2,
                                      uint32_t& r3, uint32_t addr) {
    asm volatile("ldmatrix.sync.aligned.m8n8.x4.shared.b16 {%0,%1,%2,%3}, [%4];"
                 : "=r"(r0), "=r"(r1), "=r"(r2), "=r"(r3) : "r"(addr));
}
__device__ __forceinline__ void ldsm4t(uint32_t* r, uint32_t addr) {
    asm volatile("ldmatrix.sync.aligned.m8n8.x4.trans.shared.b16 {%0,%1,%2,%3}, [%4];"
                 : "=r"(r[0]), "=r"(r[1]), "=r"(r[2]), "=r"(r[3]) : "r"(addr));
}
__device__ __forceinline__ void mma_f16(float* c, const uint32_t* a,
                                        uint32_t b0, uint32_t b1) {
    asm volatile(
        "mma.sync.aligned.m16n8k16.row.col.f32.f16.f16.f32 "
        "{%0,%1,%2,%3}, {%4,%5,%6,%7}, {%8,%9}, {%0,%1,%2,%3};"
        : "+f"(c[0]), "+f"(c[1]), "+f"(c[2]), "+f"(c[3])
        : "r"(a[0]), "r"(a[1]), "r"(a[2]), "r"(a[3]), "r"(b0), "r"(b1));
}
__device__ __forceinline__ uint32_t packh(float x, float y) {
    __half2 t = __floats2half2_rn(x, y);
    return *reinterpret_cast<uint32_t*>(&t);
}
__device__ __forceinline__ float2 unpackh(uint32_t u) {
    __half2 t = *reinterpret_cast<__half2*>(&u);
    return make_float2(__half2float(t.x), __half2float(t.y));
}

// ---------------------------------------------------------------------------
// Batched convert fp32 -> fp16: 7 jobs in one launch
// ---------------------------------------------------------------------------
struct CvtJob { const float4* src; uint2* hi; int n4; };
struct CvtJobs { CvtJob j[7]; };

__global__ void __launch_bounds__(256)
convert_all(CvtJobs jobs)
{
    const CvtJob jb = jobs.j[blockIdx.y];
    const int i = blockIdx.x * 256 + threadIdx.x;
    if (i >= jb.n4) return;
    float4 v = jb.src[i];
    __half h[4] = {__float2half_rn(v.x), __float2half_rn(v.y),
                   __float2half_rn(v.z), __float2half_rn(v.w)};
    jb.hi[i] = *reinterpret_cast<uint2*>(h);
}

// merged fp16 mask, log2 domain:
// mh[b][t][s] = fp16(log2e * amask[t][s] + (kpad[b][s] ? -60000 : 0))
__global__ void __launch_bounds__(256)
merge_mask(const float* __restrict__ am, const unsigned char* __restrict__ kp,
           __half* __restrict__ mh)
{
    const int i = blockIdx.x * 256 + threadIdx.x;
    constexpr int per_b = T_ * S_ / 4;
    const int bb = i / per_b;
    const int r  = i - bb * per_b;
    const float4 a = ((const float4*)am)[r];
    const int s = (r * 4) & (S_ - 1);
    const unsigned char* kpp = kp + bb * S_ + s;
    float f[4] = {a.x, a.y, a.z, a.w};
    __half h[4];
    #pragma unroll
    for (int j = 0; j < 4; j++)
        h[j] = __float2half_rn(LOG2E * f[j] + (kpp[j] ? -60000.f : 0.f));
    ((uint2*)mh)[i] = *reinterpret_cast<uint2*>(h);
}

// ---------------------------------------------------------------------------
// HMMA GEMM: tile 128x128, BK=32, 8 warps (warp 64x32), 2 CTAs/SM,
// 2-stage cp.async. Single-A fp16: C = A @ W^T (stage 16KB: A|W).
// OUT_MODE 0: fp16 head-major [B,H,T,D]. OUT_MODE 1: fp32 [M,E].
// ---------------------------------------------------------------------------
struct GemmJob {
    const __half *Ah, *W;
    const float* bias;
    __half *Chi;
    float* Cf;
    float scale;
};
struct GemmJobs3 { GemmJob j[3]; };

constexpr int G_STAGE = 16384;
constexpr int G_SMEM  = 2 * G_STAGE;   // 32 KB

__device__ __forceinline__ uint32_t sw_addr(int row, int byte_in_row) {
    uint32_t b = (uint32_t)(row * 64 + byte_in_row);
    return b ^ (((uint32_t)row & 3u) << 4);
}

__device__ __forceinline__ void g_load(
    uint32_t sdst, const GemmJob& jb, int bm, int bn, int k0, int tid)
{
    const __half* srcs[2] = {jb.Ah, jb.W};
    const int rbase[2] = {bm, bn};
    #pragma unroll
    for (int i = 0; i < 4; i++) {
        const int id = tid + i * 256;
        const int sub = id >> 9;
        const int lin = id & 511;
        const int row = lin >> 2, c = lin & 3;
        cp16(sdst + sub * 8192 + sw_addr(row, c * 16),
             srcs[sub] + (size_t)(rbase[sub] + row) * E_ + k0 + c * 8);
    }
}

template <int OUT_MODE>
__global__ void __launch_bounds__(256, 2)
gemm_tc(GemmJobs3 jobs)
{
    extern __shared__ char smem[];
    const uint32_t sbase = smem_u32(smem);
    const GemmJob jb = jobs.j[blockIdx.z];
    const int tid = threadIdx.x;
    const int warp = tid >> 5;
    const int lane = tid & 31;
    const int bm = blockIdx.x * 128;
    const int bn = blockIdx.y * 128;

    const int wm = (warp >> 2) * 64;
    const int wn = (warp & 3) * 32;

    float acc[4][4][4] = {};
    const int lrow = lane & 15;
    const int lseg = lane >> 4;

    g_load(sbase, jb, bm, bn, 0, tid);
    cp_commit();

    for (int chunk = 0; chunk < 32; chunk++) {
        const int s = chunk & 1;
        cp_wait<0>();
        __syncthreads();
        if (chunk < 31) {
            g_load(sbase + (s ^ 1) * G_STAGE, jb, bm, bn, (chunk + 1) * 32, tid);
            cp_commit();
        }
        const uint32_t st = sbase + s * G_STAGE;
        #pragma unroll
        for (int kk = 0; kk < 2; kk++) {
            const int c16 = (kk * 2 + lseg) * 16;
            uint32_t ah[4][4], w[2][4];
            #pragma unroll
            for (int mi = 0; mi < 4; mi++) {
                const uint32_t a = sw_addr(wm + mi * 16 + lrow, c16);
                ldsm4(ah[mi][0], ah[mi][1], ah[mi][2], ah[mi][3], st + a);
            }
            #pragma unroll
            for (int nb = 0; nb < 2; nb++) {
                const uint32_t a = sw_addr(wn + nb * 16 + lrow, c16);
                ldsm4(w[nb][0], w[nb][1], w[nb][2], w[nb][3], st + 8192 + a);
            }
            #pragma unroll
            for (int mi = 0; mi < 4; mi++) {
                #pragma unroll
                for (int ni = 0; ni < 4; ni++) {
                    const int nb = ni >> 1, hp = ni & 1;
                    mma_f16(acc[mi][ni], ah[mi], w[nb][hp], w[nb][hp + 2]);
                }
            }
        }
    }

    #pragma unroll
    for (int mi = 0; mi < 4; mi++) {
        #pragma unroll
        for (int ni = 0; ni < 4; ni++) {
            const int col = bn + wn + ni * 8 + (lane & 3) * 2;
            const float b0 = jb.bias[col], b1 = jb.bias[col + 1];
            #pragma unroll
            for (int half_ = 0; half_ < 2; half_++) {
                const int m = bm + wm + mi * 16 + (lane >> 2) + half_ * 8;
                float ox = (acc[mi][ni][half_ * 2 + 0] + b0) * jb.scale;
                float oy = (acc[mi][ni][half_ * 2 + 1] + b1) * jb.scale;
                if (OUT_MODE == 0) {
                    const int t = m >> 1, b = m & 1;   // m = t*B + b, B=2
                    const int h = col >> 6, dd = col & 63;
                    const size_t idx = ((size_t)(b * H_ + h) * T_ + t) * D_ + dd;
                    *(uint32_t*)&jb.Chi[idx] = packh(ox, oy);
                } else {
                    *(float2*)&jb.Cf[(size_t)m * E_ + col] = make_float2(ox, oy);
                }
            }
        }
    }
}

// ---------------------------------------------------------------------------
// Flash attention, fp16, log2-domain softmax (exp2 only, no mul):
// S2 = (log2e*scale)*QK + log2e*mask  [folded into Q scale + merged mask]
// P = 2^(S2 - m),  O = P·V.
// CTA: 64 q-rows of one (b,h); 4 warps x 16 rows; 128 threads; 4 CTAs/SM.
// ---------------------------------------------------------------------------
constexpr uint32_t FA_ST_B = 16384;
constexpr int FA_SMEM = 2 * 16384;   // 32768

__device__ __forceinline__ uint32_t fa_off(int row, int chunk) {
    return (uint32_t)(row * 128 + ((chunk ^ (row & 7)) << 4));
}

__device__ __forceinline__ void fa_load_stage(
    uint32_t sbase, int stage,
    const __half* __restrict__ k, const __half* __restrict__ v,
    int s0, int tid)
{
    const __half* srcs[2] = {k, v};
    #pragma unroll
    for (int i = 0; i < 8; i++) {
        const int id = tid + i * 128;
        const int sub = id >> 9;
        const int lin = id & 511;
        const int row = lin >> 3;
        const int c   = lin & 7;
        cp16(sbase + stage * FA_ST_B + sub * 8192 + fa_off(row, c),
             srcs[sub] + (size_t)(s0 + row) * D_ + c * 8);
    }
}

__global__ void __launch_bounds__(128, 4)
flash_mma(const __half* __restrict__ q_g,
          const __half* __restrict__ k_g,  const __half* __restrict__ v_g,
          const __half* __restrict__ mh_g, __half* __restrict__ ch)
{
    extern __shared__ char smem[];
    const uint32_t sbase = smem_u32(smem);
    const int tid = threadIdx.x;
    const int lane = tid & 31;
    const int warp = tid >> 5;
    const int t0 = blockIdx.x * 64;
    const int h = blockIdx.y;
    const int b = blockIdx.z;

    const size_t hoff = (size_t)(b * H_ + h);
    const __half* kk_ = k_g + hoff * S_ * D_;
    const __half* vv_ = v_g + hoff * S_ * D_;

    fa_load_stage(sbase, 0, kk_, vv_, 0, tid);
    cp_commit();

    const int wm = warp * 16;
    const int lrow = lane & 15;
    const int lseg = lane >> 4;
    const int qr = lane >> 2;
    const int qc = (lane & 3) * 2;

    // Q fragments direct from global (mma A-fragment address map)
    uint32_t qa[4][4];
    {
        const __half* q0 = q_g + (hoff * T_ + t0 + wm + qr) * D_ + qc;
        #pragma unroll
        for (int kk = 0; kk < 4; kk++) {
            qa[kk][0] = *(const uint32_t*)&q0[kk * 16];
            qa[kk][1] = *(const uint32_t*)&q0[8 * D_ + kk * 16];
            qa[kk][2] = *(const uint32_t*)&q0[kk * 16 + 8];
            qa[kk][3] = *(const uint32_t*)&q0[8 * D_ + kk * 16 + 8];
        }
    }

    float acc[8][4] = {};
    float l0 = 0.f, l1 = 0.f;
    float m0 = -1e30f, m1 = -1e30f;

    const __half* mrow0 = mh_g + ((size_t)b * T_ + t0 + wm + qr) * S_ + qc;
    const __half* mrow1 = mrow0 + 8 * S_;

    for (int tile = 0; tile < 32; tile++) {
        const int stg = tile & 1;
        cp_wait<0>();
        __syncthreads();
        if (tile < 31) {
            fa_load_stage(sbase, stg ^ 1, kk_, vv_, (tile + 1) * 64, tid);
            cp_commit();
        }

        const uint32_t stk = sbase + stg * FA_ST_B;

        // ---- scores (log2 domain; Q pre-scaled by 0.125*log2e) ----
        float sc[8][4];
        #pragma unroll
        for (int j = 0; j < 8; j++) {
            sc[j][0] = 0.f; sc[j][1] = 0.f; sc[j][2] = 0.f; sc[j][3] = 0.f;
        }
        #pragma unroll
        for (int kk = 0; kk < 4; kk++) {
            #pragma unroll
            for (int nb = 0; nb < 4; nb++) {
                uint32_t bh[4];
                const uint32_t a = fa_off(nb * 16 + lrow, kk * 2 + lseg);
                ldsm4(bh[0], bh[1], bh[2], bh[3], stk + a);
                mma_f16(sc[nb * 2 + 0], qa[kk], bh[0], bh[2]);
                mma_f16(sc[nb * 2 + 1], qa[kk], bh[1], bh[3]);
            }
        }

        // ---- merged mask (log2e-scaled fp16, direct global) ----
        const int scol = tile * 64;
        #pragma unroll
        for (int j = 0; j < 8; j++) {
            float2 a0 = unpackh(*(const uint32_t*)&mrow0[scol + j * 8]);
            float2 a1 = unpackh(*(const uint32_t*)&mrow1[scol + j * 8]);
            sc[j][0] += a0.x; sc[j][1] += a0.y;
            sc[j][2] += a1.x; sc[j][3] += a1.y;
        }

        // ---- online softmax in base-2 ----
        float tm0 = -1e30f, tm1 = -1e30f;
        #pragma unroll
        for (int j = 0; j < 8; j++) {
            tm0 = fmaxf(tm0, fmaxf(sc[j][0], sc[j][1]));
            tm1 = fmaxf(tm1, fmaxf(sc[j][2], sc[j][3]));
        }
        tm0 = fmaxf(tm0, __shfl_xor_sync(0xffffffffu, tm0, 1, 4));
        tm0 = fmaxf(tm0, __shfl_xor_sync(0xffffffffu, tm0, 2, 4));
        tm1 = fmaxf(tm1, __shfl_xor_sync(0xffffffffu, tm1, 1, 4));
        tm1 = fmaxf(tm1, __shfl_xor_sync(0xffffffffu, tm1, 2, 4));
        const float mn0 = fmaxf(m0, tm0), mn1 = fmaxf(m1, tm1);
        const float cr0 = exp2f(m0 - mn0), cr1 = exp2f(m1 - mn1);
        m0 = mn0; m1 = mn1;
        float rs0 = 0.f, rs1 = 0.f;
        #pragma unroll
        for (int j = 0; j < 8; j++) {
            sc[j][0] = exp2f(sc[j][0] - mn0);
            sc[j][1] = exp2f(sc[j][1] - mn0);
            sc[j][2] = exp2f(sc[j][2] - mn1);
            sc[j][3] = exp2f(sc[j][3] - mn1);
            rs0 += sc[j][0] + sc[j][1];
            rs1 += sc[j][2] + sc[j][3];
        }
        rs0 += __shfl_xor_sync(0xffffffffu, rs0, 1, 4);
        rs0 += __shfl_xor_sync(0xffffffffu, rs0, 2, 4);
        rs1 += __shfl_xor_sync(0xffffffffu, rs1, 1, 4);
        rs1 += __shfl_xor_sync(0xffffffffu, rs1, 2, 4);
        l0 = l0 * cr0 + rs0;
        l1 = l1 * cr1 + rs1;
        #pragma unroll
        for (int j = 0; j < 8; j++) {
            acc[j][0] *= cr0; acc[j][1] *= cr0;
            acc[j][2] *= cr1; acc[j][3] *= cr1;
        }

        // ---- PV: O += P . V ----
        #pragma unroll
        for (int kk = 0; kk < 4; kk++) {
            const int j0 = 2 * kk, j1 = j0 + 1;
            uint32_t ph[4];
            ph[0] = packh(sc[j0][0], sc[j0][1]);
            ph[1] = packh(sc[j0][2], sc[j0][3]);
            ph[2] = packh(sc[j1][0], sc[j1][1]);
            ph[3] = packh(sc[j1][2], sc[j1][3]);
            #pragma unroll
            for (int ng = 0; ng < 4; ng++) {
                uint32_t v4[4];
                const uint32_t a = fa_off(kk * 16 + lrow, ng * 2 + lseg);
                ldsm4t(v4, stk + 8192 + a);
                mma_f16(acc[ng * 2 + 0], ph, v4[0], v4[1]);
                mma_f16(acc[ng * 2 + 1], ph, v4[2], v4[3]);
            }
        }
    }

    // ---- epilogue: normalize, write ctx fp16 [t*B+b][E] ----
    const float inv0 = 1.f / l0, inv1 = 1.f / l1;
    const int r0 = t0 + wm + qr, r1 = r0 + 8;
    #pragma unroll
    for (int j = 0; j < 8; j++) {
        const int col = h * D_ + j * 8 + qc;
        *(uint32_t*)&ch[((size_t)r0 * B_ + b) * E_ + col] =
            packh(acc[j][0] * inv0, acc[j][1] * inv0);
        *(uint32_t*)&ch[((size_t)r1 * B_ + b) * E_ + col] =
            packh(acc[j][2] * inv1, acc[j][3] * inv1);
    }
}

// ---------------------------------------------------------------------------
// Launch
// ---------------------------------------------------------------------------
extern "C" void kernel_launch(void* const* d_in, const int* in_sizes, int n_in,
                              void* d_out, int out_size)
{
    const float* query = (const float*)d_in[0];
    const float* key   = (const float*)d_in[1];
    const float* value = (const float*)d_in[2];
    const float* amask = (const float*)d_in[3];
    const unsigned char* kpad = (const unsigned char*)d_in[4];
    const float* Wq = (const float*)d_in[5];
    const float* bq = (const float*)d_in[6];
    const float* Wk = (const float*)d_in[7];
    const float* bk = (const float*)d_in[8];
    const float* Wv = (const float*)d_in[9];
    const float* bv = (const float*)d_in[10];
    const float* Wo = (const float*)d_in[11];
    const float* bo = (const float*)d_in[12];
    float* out = (float*)d_out;

    __half *iq, *ik, *iv, *w;
    __half *pq, *pk, *pv, *ch, *mh;
    cudaGetSymbolAddress((void**)&iq, g_iq);
    cudaGetSymbolAddress((void**)&ik, g_ik);
    cudaGetSymbolAddress((void**)&iv, g_iv);
    cudaGetSymbolAddress((void**)&w, g_w);
    cudaGetSymbolAddress((void**)&pq, g_pq);
    cudaGetSymbolAddress((void**)&pk, g_pk);   cudaGetSymbolAddress((void**)&pv, g_pv);
    cudaGetSymbolAddress((void**)&ch, g_ch);
    cudaGetSymbolAddress((void**)&mh, g_mh);

    cudaFuncSetAttribute((const void*)gemm_tc<0>, cudaFuncAttributeMaxDynamicSharedMemorySize, G_SMEM);
    cudaFuncSetAttribute((const void*)gemm_tc<1>, cudaFuncAttributeMaxDynamicSharedMemorySize, G_SMEM);
    cudaFuncSetAttribute((const void*)flash_mma, cudaFuncAttributeMaxDynamicSharedMemorySize, FA_SMEM);

    const int nIn4 = M_ * E_ / 4;
    const int nW4  = E_ * E_ / 4;

    CvtJobs cj;
    cj.j[0] = {(const float4*)query, (uint2*)iq, nIn4};
    cj.j[1] = {(const float4*)key,   (uint2*)ik, nIn4};
    cj.j[2] = {(const float4*)value, (uint2*)iv, nIn4};
    cj.j[3] = {(const float4*)Wq, (uint2*)(w + 0 * E_ * E_), nW4};
    cj.j[4] = {(const float4*)Wk, (uint2*)(w + 1 * E_ * E_), nW4};
    cj.j[5] = {(const float4*)Wv, (uint2*)(w + 2 * E_ * E_), nW4};
    cj.j[6] = {(const float4*)Wo, (uint2*)(w + 3 * E_ * E_), nW4};
    convert_all<<<dim3(nIn4 / 256, 7), 256>>>(cj);
    merge_mask<<<B_ * T_ * S_ / 4 / 256, 256>>>(amask, kpad, mh);

    // Fused Q/K/V projections (Q scale folds 1/sqrt(d) AND log2e).
    GemmJobs3 gqkv;
    gqkv.j[0] = {iq, w + 0 * E_ * E_, bq, pq, nullptr, 0.125f * LOG2E};
    gqkv.j[1] = {ik, w + 1 * E_ * E_, bk, pk, nullptr, 1.0f};
    gqkv.j[2] = {iv, w + 2 * E_ * E_, bv, pv, nullptr, 1.0f};
    gemm_tc<0><<<dim3(M_ / 128, E_ / 128, 3), 256, G_SMEM>>>(gqkv);

    // flash attention: 64-row CTAs, 128 threads, 4 CTAs/SM
    dim3 fgrid(T_ / 64, H_, B_);
    flash_mma<<<fgrid, 128, FA_SMEM>>>(pq, pk, pv, mh, ch);

    // output projection (fp32 out)
    GemmJobs3 go;
    go.j[0] = {ch, w + 3 * E_ * E_, bo, nullptr, out, 1.0f};
    go.j[1] = go.j[0];
    go.j[2] = go.j[0];
    gemm_tc<1><<<dim3(M_ / 128, E_ / 128, 1), 256, G_SMEM>>>(go);
}

// round 17
// speedup vs baseline: 1.1962x; 1.1962x over previous
#include <cuda_runtime.h>
#include <cuda_fp16.h>
#include <cstdint>

// Problem constants (fixed shapes)
constexpr int T_ = 2048;
constexpr int S_ = 2048;
constexpr int B_ = 2;
constexpr int E_ = 1024;
constexpr int H_ = 16;
constexpr int D_ = 64;
constexpr int M_ = T_ * B_;   // 4096

constexpr float LOG2E = 1.44269504088896f;

// ---------------------------------------------------------------------------
// Scratch (__device__ globals; allocations forbidden)
// ---------------------------------------------------------------------------
__device__ __half g_iq[M_ * E_];
__device__ __half g_ik[M_ * E_];
__device__ __half g_iv[M_ * E_];
__device__ __half g_w[4][E_ * E_];
__device__ __half g_pq[B_ * H_ * T_ * D_];   // Q single (pre-scaled by 0.125*log2e)
__device__ __half g_pk[B_ * H_ * S_ * D_];
__device__ __half g_pv[B_ * H_ * S_ * D_];
__device__ __half g_ch[M_ * E_];
__device__ __half g_mh[B_ * T_ * S_];        // merged mask, log2e-scaled

// ---------------------------------------------------------------------------
// PTX helpers (generic PTX only)
// ---------------------------------------------------------------------------
__device__ __forceinline__ uint32_t smem_u32(const void* p) {
    uint32_t a;
    asm("{ .reg .u64 t; cvta.to.shared.u64 t, %1; cvt.u32.u64 %0, t; }"
        : "=r"(a) : "l"(p));
    return a;
}
__device__ __forceinline__ void cp16(uint32_t dst, const void* src) {
    asm volatile("cp.async.cg.shared.global [%0], [%1], 16;" :: "r"(dst), "l"(src));
}
__device__ __forceinline__ void cp_commit() {
    asm volatile("cp.async.commit_group;" ::: "memory");
}
template <int N>
__device__ __forceinline__ void cp_wait() {
    asm volatile("cp.async.wait_group %0;" :: "n"(N) : "memory");
}
__device__ __forceinline__ void ldsm4(uint32_t& r0, uint32_t& r1, uint32_t& r2,
                                      uint32_t& r3, uint32_t addr) {
    asm volatile("ldmatrix.sync.aligned.m8n8.x4.shared.b16 {%0,%1,%2,%3}, [%4];"
                 : "=r"(r0), "=r"(r1), "=r"(r2), "=r"(r3) : "r"(addr));
}
__device__ __forceinline__ void ldsm4t(uint32_t* r, uint32_t addr) {
    asm volatile("ldmatrix.sync.aligned.m8n8.x4.trans.shared.b16 {%0,%1,%2,%3}, [%4];"
                 : "=r"(r[0]), "=r"(r[1]), "=r"(r[2]), "=r"(r[3]) : "r"(addr));
}
__device__ __forceinline__ void mma_f16(float* c, const uint32_t* a,
                                        uint32_t b0, uint32_t b1) {
    asm volatile(
        "mma.sync.aligned.m16n8k16.row.col.f32.f16.f16.f32 "
        "{%0,%1,%2,%3}, {%4,%5,%6,%7}, {%8,%9}, {%0,%1,%2,%3};"
        : "+f"(c[0]), "+f"(c[1]), "+f"(c[2]), "+f"(c[3])
        : "r"(a[0]), "r"(a[1]), "r"(a[2]), "r"(a[3]), "r"(b0), "r"(b1));
}
__device__ __forceinline__ uint32_t packh(float x, float y) {
    __half2 t = __floats2half2_rn(x, y);
    return *reinterpret_cast<uint32_t*>(&t);
}
__device__ __forceinline__ float2 unpackh(uint32_t u) {
    __half2 t = *reinterpret_cast<__half2*>(&u);
    return make_float2(__half2float(t.x), __half2float(t.y));
}

// ---------------------------------------------------------------------------
// Batched convert fp32 -> fp16: 7 jobs in one launch
// ---------------------------------------------------------------------------
struct CvtJob { const float4* src; uint2* hi; int n4; };
struct CvtJobs { CvtJob j[7]; };

__global__ void __launch_bounds__(256)
convert_all(CvtJobs jobs)
{
    const CvtJob jb = jobs.j[blockIdx.y];
    const int i = blockIdx.x * 256 + threadIdx.x;
    if (i >= jb.n4) return;
    float4 v = jb.src[i];
    __half h[4] = {__float2half_rn(v.x), __float2half_rn(v.y),
                   __float2half_rn(v.z), __float2half_rn(v.w)};
    jb.hi[i] = *reinterpret_cast<uint2*>(h);
}

// merged fp16 mask, log2 domain:
// mh[b][t][s] = fp16(log2e * amask[t][s] + (kpad[b][s] ? -60000 : 0))
__global__ void __launch_bounds__(256)
merge_mask(const float* __restrict__ am, const unsigned char* __restrict__ kp,
           __half* __restrict__ mh)
{
    const int i = blockIdx.x * 256 + threadIdx.x;
    constexpr int per_b = T_ * S_ / 4;
    const int bb = i / per_b;
    const int r  = i - bb * per_b;
    const float4 a = ((const float4*)am)[r];
    const int s = (r * 4) & (S_ - 1);
    const unsigned char* kpp = kp + bb * S_ + s;
    float f[4] = {a.x, a.y, a.z, a.w};
    __half h[4];
    #pragma unroll
    for (int j = 0; j < 4; j++)
        h[j] = __float2half_rn(LOG2E * f[j] + (kpp[j] ? -60000.f : 0.f));
    ((uint2*)mh)[i] = *reinterpret_cast<uint2*>(h);
}

// ---------------------------------------------------------------------------
// HMMA GEMM: tile 128x128, BK=32, 8 warps (warp 64x32), 2 CTAs/SM,
// 2-stage cp.async. Single-A fp16: C = A @ W^T (stage 16KB: A|W).
// OUT_MODE 0: fp16 head-major [B,H,T,D]. OUT_MODE 1: fp32 [M,E].
// ---------------------------------------------------------------------------
struct GemmJob {
    const __half *Ah, *W;
    const float* bias;
    __half *Chi;
    float* Cf;
    float scale;
};
struct GemmJobs3 { GemmJob j[3]; };

constexpr int G_STAGE = 16384;
constexpr int G_SMEM  = 2 * G_STAGE;   // 32 KB

__device__ __forceinline__ uint32_t sw_addr(int row, int byte_in_row) {
    uint32_t b = (uint32_t)(row * 64 + byte_in_row);
    return b ^ (((uint32_t)row & 3u) << 4);
}

__device__ __forceinline__ void g_load(
    uint32_t sdst, const GemmJob& jb, int bm, int bn, int k0, int tid)
{
    const __half* srcs[2] = {jb.Ah, jb.W};
    const int rbase[2] = {bm, bn};
    #pragma unroll
    for (int i = 0; i < 4; i++) {
        const int id = tid + i * 256;
        const int sub = id >> 9;
        const int lin = id & 511;
        const int row = lin >> 2, c = lin & 3;
        cp16(sdst + sub * 8192 + sw_addr(row, c * 16),
             srcs[sub] + (size_t)(rbase[sub] + row) * E_ + k0 + c * 8);
    }
}

template <int OUT_MODE>
__global__ void __launch_bounds__(256, 2)
gemm_tc(GemmJobs3 jobs)
{
    extern __shared__ char smem[];
    const uint32_t sbase = smem_u32(smem);
    const GemmJob jb = jobs.j[blockIdx.z];
    const int tid = threadIdx.x;
    const int warp = tid >> 5;
    const int lane = tid & 31;
    const int bm = blockIdx.x * 128;
    const int bn = blockIdx.y * 128;

    const int wm = (warp >> 2) * 64;
    const int wn = (warp & 3) * 32;

    float acc[4][4][4] = {};
    const int lrow = lane & 15;
    const int lseg = lane >> 4;

    g_load(sbase, jb, bm, bn, 0, tid);
    cp_commit();

    for (int chunk = 0; chunk < 32; chunk++) {
        const int s = chunk & 1;
        cp_wait<0>();
        __syncthreads();
        if (chunk < 31) {
            g_load(sbase + (s ^ 1) * G_STAGE, jb, bm, bn, (chunk + 1) * 32, tid);
            cp_commit();
        }
        const uint32_t st = sbase + s * G_STAGE;
        #pragma unroll
        for (int kk = 0; kk < 2; kk++) {
            const int c16 = (kk * 2 + lseg) * 16;
            uint32_t ah[4][4], w[2][4];
            #pragma unroll
            for (int mi = 0; mi < 4; mi++) {
                const uint32_t a = sw_addr(wm + mi * 16 + lrow, c16);
                ldsm4(ah[mi][0], ah[mi][1], ah[mi][2], ah[mi][3], st + a);
            }
            #pragma unroll
            for (int nb = 0; nb < 2; nb++) {
                const uint32_t a = sw_addr(wn + nb * 16 + lrow, c16);
                ldsm4(w[nb][0], w[nb][1], w[nb][2], w[nb][3], st + 8192 + a);
            }
            #pragma unroll
            for (int mi = 0; mi < 4; mi++) {
                #pragma unroll
                for (int ni = 0; ni < 4; ni++) {
                    const int nb = ni >> 1, hp = ni & 1;
                    mma_f16(acc[mi][ni], ah[mi], w[nb][hp], w[nb][hp + 2]);
                }
            }
        }
    }

    #pragma unroll
    for (int mi = 0; mi < 4; mi++) {
        #pragma unroll
        for (int ni = 0; ni < 4; ni++) {
            const int col = bn + wn + ni * 8 + (lane & 3) * 2;
            const float b0 = jb.bias[col], b1 = jb.bias[col + 1];
            #pragma unroll
            for (int half_ = 0; half_ < 2; half_++) {
                const int m = bm + wm + mi * 16 + (lane >> 2) + half_ * 8;
                float ox = (acc[mi][ni][half_ * 2 + 0] + b0) * jb.scale;
                float oy = (acc[mi][ni][half_ * 2 + 1] + b1) * jb.scale;
                if (OUT_MODE == 0) {
                    const int t = m >> 1, b = m & 1;   // m = t*B + b, B=2
                    const int h = col >> 6, dd = col & 63;
                    const size_t idx = ((size_t)(b * H_ + h) * T_ + t) * D_ + dd;
                    *(uint32_t*)&jb.Chi[idx] = packh(ox, oy);
                } else {
                    *(float2*)&jb.Cf[(size_t)m * E_ + col] = make_float2(ox, oy);
                }
            }
        }
    }
}

// ---------------------------------------------------------------------------
// Flash attention, fp16, log2-domain softmax. Mask staged through the
// cp.async pipeline (stage: K 8KB | V 8KB | mask 8KB = 24KB; 2 stages 48KB).
// CTA: 64 q-rows of one (b,h); 4 warps x 16 rows; 128 threads; 3 CTAs/SM.
// ---------------------------------------------------------------------------
constexpr uint32_t FA_ST_B   = 24576;
constexpr uint32_t FA_M_OFF  = 16384;   // mask within stage
constexpr int FA_SMEM = 2 * (int)FA_ST_B;   // 49152

__device__ __forceinline__ uint32_t fa_off(int row, int chunk) {
    return (uint32_t)(row * 128 + ((chunk ^ (row & 7)) << 4));
}

__device__ __forceinline__ void fa_load_stage(
    uint32_t sbase, int stage,
    const __half* __restrict__ k, const __half* __restrict__ v,
    const __half* __restrict__ mrow_base,   // mh + (b*T + t0)*S
    int s0, int tid)
{
    const uint32_t sdst = sbase + stage * FA_ST_B;
    const __half* srcs[2] = {k, v};
    #pragma unroll
    for (int i = 0; i < 8; i++) {
        const int id = tid + i * 128;       // 0..1023
        const int sub = id >> 9;
        const int lin = id & 511;
        const int row = lin >> 3;
        const int c   = lin & 7;
        cp16(sdst + sub * 8192 + fa_off(row, c),
             srcs[sub] + (size_t)(s0 + row) * D_ + c * 8);
    }
    // mask tile: 64 q-rows x 64 keys fp16, same XOR swizzle (conflict-free LDS)
    #pragma unroll
    for (int i = 0; i < 4; i++) {
        const int id = tid + i * 128;       // 0..511
        const int row = id >> 3;
        const int c   = id & 7;
        cp16(sdst + FA_M_OFF + fa_off(row, c),
             mrow_base + (size_t)row * S_ + s0 + c * 8);
    }
}

__global__ void __launch_bounds__(128, 3)
flash_mma(const __half* __restrict__ q_g,
          const __half* __restrict__ k_g,  const __half* __restrict__ v_g,
          const __half* __restrict__ mh_g, __half* __restrict__ ch)
{
    extern __shared__ char smem[];
    const uint32_t sbase = smem_u32(smem);
    const int tid = threadIdx.x;
    const int lane = tid & 31;
    const int warp = tid >> 5;
    const int t0 = blockIdx.x * 64;
    const int h = blockIdx.y;
    const int b = blockIdx.z;

    const size_t hoff = (size_t)(b * H_ + h);
    const __half* kk_ = k_g + hoff * S_ * D_;
    const __half* vv_ = v_g + hoff * S_ * D_;
    const __half* mbase = mh_g + ((size_t)b * T_ + t0) * S_;

    fa_load_stage(sbase, 0, kk_, vv_, mbase, 0, tid);
    cp_commit();

    const int wm = warp * 16;
    const int lrow = lane & 15;
    const int lseg = lane >> 4;
    const int qr = lane >> 2;
    const int qc = (lane & 3) * 2;

    // Q fragments direct from global (mma A-fragment address map)
    uint32_t qa[4][4];
    {
        const __half* q0 = q_g + (hoff * T_ + t0 + wm + qr) * D_ + qc;
        #pragma unroll
        for (int kk = 0; kk < 4; kk++) {
            qa[kk][0] = *(const uint32_t*)&q0[kk * 16];
            qa[kk][1] = *(const uint32_t*)&q0[8 * D_ + kk * 16];
            qa[kk][2] = *(const uint32_t*)&q0[kk * 16 + 8];
            qa[kk][3] = *(const uint32_t*)&q0[8 * D_ + kk * 16 + 8];
        }
    }

    float acc[8][4] = {};
    float l0 = 0.f, l1 = 0.f;
    float m0 = -1e30f, m1 = -1e30f;

    for (int tile = 0; tile < 32; tile++) {
        const int stg = tile & 1;
        cp_wait<0>();
        __syncthreads();
        if (tile < 31) {
            fa_load_stage(sbase, stg ^ 1, kk_, vv_, mbase, (tile + 1) * 64, tid);
            cp_commit();
        }

        const uint32_t stk = sbase + stg * FA_ST_B;

        // ---- scores (log2 domain; Q pre-scaled by 0.125*log2e) ----
        float sc[8][4];
        #pragma unroll
        for (int j = 0; j < 8; j++) {
            sc[j][0] = 0.f; sc[j][1] = 0.f; sc[j][2] = 0.f; sc[j][3] = 0.f;
        }
        #pragma unroll
        for (int kk = 0; kk < 4; kk++) {
            #pragma unroll
            for (int nb = 0; nb < 4; nb++) {
                uint32_t bh[4];
                const uint32_t a = fa_off(nb * 16 + lrow, kk * 2 + lseg);
                ldsm4(bh[0], bh[1], bh[2], bh[3], stk + a);
                mma_f16(sc[nb * 2 + 0], qa[kk], bh[0], bh[2]);
                mma_f16(sc[nb * 2 + 1], qa[kk], bh[1], bh[3]);
            }
        }

        // ---- merged mask from smem (swizzled, conflict-free) ----
        {
            const uint32_t mbase_s = stk + FA_M_OFF;
            const int r0 = wm + qr, r1 = r0 + 8;
            #pragma unroll
            for (int j = 0; j < 8; j++) {
                uint32_t u0 = *(const uint32_t*)(smem + (mbase_s - sbase) +
                                                 fa_off(r0, j) + qc * 2);
                uint32_t u1 = *(const uint32_t*)(smem + (mbase_s - sbase) +
                                                 fa_off(r1, j) + qc * 2);
                float2 a0 = unpackh(u0);
                float2 a1 = unpackh(u1);
                sc[j][0] += a0.x; sc[j][1] += a0.y;
                sc[j][2] += a1.x; sc[j][3] += a1.y;
            }
        }

        // ---- online softmax in base-2 ----
        float tm0 = -1e30f, tm1 = -1e30f;
        #pragma unroll
        for (int j = 0; j < 8; j++) {
            tm0 = fmaxf(tm0, fmaxf(sc[j][0], sc[j][1]));
            tm1 = fmaxf(tm1, fmaxf(sc[j][2], sc[j][3]));
        }
        tm0 = fmaxf(tm0, __shfl_xor_sync(0xffffffffu, tm0, 1, 4));
        tm0 = fmaxf(tm0, __shfl_xor_sync(0xffffffffu, tm0, 2, 4));
        tm1 = fmaxf(tm1, __shfl_xor_sync(0xffffffffu, tm1, 1, 4));
        tm1 = fmaxf(tm1, __shfl_xor_sync(0xffffffffu, tm1, 2, 4));
        const float mn0 = fmaxf(m0, tm0), mn1 = fmaxf(m1, tm1);
        const float cr0 = exp2f(m0 - mn0), cr1 = exp2f(m1 - mn1);
        m0 = mn0; m1 = mn1;
        float rs0 = 0.f, rs1 = 0.f;
        #pragma unroll
        for (int j = 0; j < 8; j++) {
            sc[j][0] = exp2f(sc[j][0] - mn0);
            sc[j][1] = exp2f(sc[j][1] - mn0);
            sc[j][2] = exp2f(sc[j][2] - mn1);
            sc[j][3] = exp2f(sc[j][3] - mn1);
            rs0 += sc[j][0] + sc[j][1];
            rs1 += sc[j][2] + sc[j][3];
        }
        rs0 += __shfl_xor_sync(0xffffffffu, rs0, 1, 4);
        rs0 += __shfl_xor_sync(0xffffffffu, rs0, 2, 4);
        rs1 += __shfl_xor_sync(0xffffffffu, rs1, 1, 4);
        rs1 += __shfl_xor_sync(0xffffffffu, rs1, 2, 4);
        l0 = l0 * cr0 + rs0;
        l1 = l1 * cr1 + rs1;
        #pragma unroll
        for (int j = 0; j < 8; j++) {
            acc[j][0] *= cr0; acc[j][1] *= cr0;
            acc[j][2] *= cr1; acc[j][3] *= cr1;
        }

        // ---- PV: O += P . V ----
        #pragma unroll
        for (int kk = 0; kk < 4; kk++) {
            const int j0 = 2 * kk, j1 = j0 + 1;
            uint32_t ph[4];
            ph[0] = packh(sc[j0][0], sc[j0][1]);
            ph[1] = packh(sc[j0][2], sc[j0][3]);
            ph[2] = packh(sc[j1][0], sc[j1][1]);
            ph[3] = packh(sc[j1][2], sc[j1][3]);
            #pragma unroll
            for (int ng = 0; ng < 4; ng++) {
                uint32_t v4[4];
                const uint32_t a = fa_off(kk * 16 + lrow, ng * 2 + lseg);
                ldsm4t(v4, stk + 8192 + a);
                mma_f16(acc[ng * 2 + 0], ph, v4[0], v4[1]);
                mma_f16(acc[ng * 2 + 1], ph, v4[2], v4[3]);
            }
        }
    }

    // ---- epilogue: normalize, write ctx fp16 [t*B+b][E] ----
    const float inv0 = 1.f / l0, inv1 = 1.f / l1;
    const int r0 = t0 + wm + qr, r1 = r0 + 8;
    #pragma unroll
    for (int j = 0; j < 8; j++) {
        const int col = h * D_ + j * 8 + qc;
        *(uint32_t*)&ch[((size_t)r0 * B_ + b) * E_ + col] =
            packh(acc[j][0] * inv0, acc[j][1] * inv0);
        *(uint32_t*)&ch[((size_t)r1 * B_ + b) * E_ + col] =
            packh(acc[j][2] * inv1, acc[j][3] * inv1);
    }
}

// ---------------------------------------------------------------------------
// Launch
// ---------------------------------------------------------------------------
extern "C" void kernel_launch(void* const* d_in, const int* in_sizes, int n_in,
                              void* d_out, int out_size)
{
    const float* query = (const float*)d_in[0];
    const float* key   = (const float*)d_in[1];
    const float* value = (const float*)d_in[2];
    const float* amask = (const float*)d_in[3];
    const unsigned char* kpad = (const unsigned char*)d_in[4];
    const float* Wq = (const float*)d_in[5];
    const float* bq = (const float*)d_in[6];
    const float* Wk = (const float*)d_in[7];
    const float* bk = (const float*)d_in[8];
    const float* Wv = (const float*)d_in[9];
    const float* bv = (const float*)d_in[10];
    const float* Wo = (const float*)d_in[11];
    const float* bo = (const float*)d_in[12];
    float* out = (float*)d_out;

    __half *iq, *ik, *iv, *w;
    __half *pq, *pk, *pv, *ch, *mh;
    cudaGetSymbolAddress((void**)&iq, g_iq);
    cudaGetSymbolAddress((void**)&ik, g_ik);
    cudaGetSymbolAddress((void**)&iv, g_iv);
    cudaGetSymbolAddress((void**)&w, g_w);
    cudaGetSymbolAddress((void**)&pq, g_pq);
    cudaGetSymbolAddress((void**)&pk, g_pk);   cudaGetSymbolAddress((void**)&pv, g_pv);
    cudaGetSymbolAddress((void**)&ch, g_ch);
    cudaGetSymbolAddress((void**)&mh, g_mh);

    cudaFuncSetAttribute((const void*)gemm_tc<0>, cudaFuncAttributeMaxDynamicSharedMemorySize, G_SMEM);
    cudaFuncSetAttribute((const void*)gemm_tc<1>, cudaFuncAttributeMaxDynamicSharedMemorySize, G_SMEM);
    cudaFuncSetAttribute((const void*)flash_mma, cudaFuncAttributeMaxDynamicSharedMemorySize, FA_SMEM);

    const int nIn4 = M_ * E_ / 4;
    const int nW4  = E_ * E_ / 4;

    CvtJobs cj;
    cj.j[0] = {(const float4*)query, (uint2*)iq, nIn4};
    cj.j[1] = {(const float4*)key,   (uint2*)ik, nIn4};
    cj.j[2] = {(const float4*)value, (uint2*)iv, nIn4};
    cj.j[3] = {(const float4*)Wq, (uint2*)(w + 0 * E_ * E_), nW4};
    cj.j[4] = {(const float4*)Wk, (uint2*)(w + 1 * E_ * E_), nW4};
    cj.j[5] = {(const float4*)Wv, (uint2*)(w + 2 * E_ * E_), nW4};
    cj.j[6] = {(const float4*)Wo, (uint2*)(w + 3 * E_ * E_), nW4};
    convert_all<<<dim3(nIn4 / 256, 7), 256>>>(cj);
    merge_mask<<<B_ * T_ * S_ / 4 / 256, 256>>>(amask, kpad, mh);

    // Fused Q/K/V projections (Q scale folds 1/sqrt(d) AND log2e).
    GemmJobs3 gqkv;
    gqkv.j[0] = {iq, w + 0 * E_ * E_, bq, pq, nullptr, 0.125f * LOG2E};
    gqkv.j[1] = {ik, w + 1 * E_ * E_, bk, pk, nullptr, 1.0f};
    gqkv.j[2] = {iv, w + 2 * E_ * E_, bv, pv, nullptr, 1.0f};
    gemm_tc<0><<<dim3(M_ / 128, E_ / 128, 3), 256, G_SMEM>>>(gqkv);

    // flash attention: 64-row CTAs, 128 threads, 3 CTAs/SM
    dim3 fgrid(T_ / 64, H_, B_);
    flash_mma<<<fgrid, 128, FA_SMEM>>>(pq, pk, pv, mh, ch);

    // output projection (fp32 out)
    GemmJobs3 go;
    go.j[0] = {ch, w + 3 * E_ * E_, bo, nullptr, out, 1.0f};
    go.j[1] = go.j[0];
    go.j[2] = go.j[0];
    gemm_tc<1><<<dim3(M_ / 128, E_ / 128, 1), 256, G_SMEM>>>(go);
}